// round 5
// baseline (speedup 1.0000x reference)
#include <cuda_runtime.h>
#include <cstdint>

#define NN 20000
#define NE 320000
#define NG 512

// ---------------- scratch (device globals; no allocation allowed) ----------
__device__ float g_bufA[NN * 1024];
__device__ float g_bufB[NN * 1024];
__device__ float g_deg[NN];
__device__ float g_dinv[NN];
__device__ float g_enorm[NE];
__device__ int   g_cnt[NN];
__device__ int   g_rowptr[NN + 1];
__device__ int   g_cursor[NN];
__device__ int   g_esrc[NE];
__device__ float g_ew[NE];
__device__ float g_ps[1024];
__device__ float g_pq[1024];
__device__ float g_aA[5 * 1024];
__device__ float g_aD[5 * 1024];
__device__ float g_gate[NN];
__device__ float g_gmax[NG];
__device__ float g_gsum[NG];
__device__ float g_pool[NG * 1024];
__device__ float g_p2[NG * 128];
__device__ float g_p3[NG * 16];

// ---------------- small utility kernels ------------------------------------
__global__ void k_fill(float* p, long n, float v) {
    long i = (long)blockIdx.x * blockDim.x + threadIdx.x;
    if (i < n) p[i] = v;
}
__global__ void k_filli(int* p, int n, int v) {
    int i = blockIdx.x * blockDim.x + threadIdx.x;
    if (i < n) p[i] = v;
}

__global__ void k_deg(const int* __restrict__ col, float* __restrict__ deg) {
    int e = blockIdx.x * blockDim.x + threadIdx.x;
    if (e < NE) atomicAdd(&deg[col[e]], 1.0f);
}

__global__ void k_dinv(const float* __restrict__ deg, float* __restrict__ dinv,
                       int* __restrict__ cnt) {
    int i = blockIdx.x * blockDim.x + threadIdx.x;
    if (i < NN) {
        dinv[i] = rsqrtf(deg[i]);
        cnt[i] = (int)(deg[i] - 0.5f);   // in-degree (deg includes self +1)
    }
}

__global__ void k_enorm(const int* __restrict__ row, const int* __restrict__ col,
                        const float* __restrict__ dinv, float* __restrict__ nrm) {
    int e = blockIdx.x * blockDim.x + threadIdx.x;
    if (e < NE) nrm[e] = dinv[row[e]] * dinv[col[e]];
}

// single-block exclusive scan of cnt -> rowptr  (chunked Hillis-Steele)
__global__ void k_scan(const int* __restrict__ cnt, int* __restrict__ rowptr) {
    __shared__ int s[1024];
    const int CH = 20;
    int t = threadIdx.x;
    int base = t * CH;
    int sum = 0;
    for (int i = 0; i < CH; i++) {
        int idx = base + i;
        if (idx < NN) sum += cnt[idx];
    }
    s[t] = sum;
    __syncthreads();
    for (int off = 1; off < 1024; off <<= 1) {
        int v = (t >= off) ? s[t - off] : 0;
        __syncthreads();
        s[t] += v;
        __syncthreads();
    }
    int excl = (t == 0) ? 0 : s[t - 1];
    int run = excl;
    for (int i = 0; i < CH; i++) {
        int idx = base + i;
        if (idx < NN) { rowptr[idx] = run; run += cnt[idx]; }
    }
    if (t == 1023) rowptr[NN] = s[1023];
}

__global__ void k_scatter(const int* __restrict__ row, const int* __restrict__ col,
                          const float* __restrict__ nrm, const int* __restrict__ rowptr,
                          int* __restrict__ cursor, int* __restrict__ esrc,
                          float* __restrict__ ew) {
    int e = blockIdx.x * blockDim.x + threadIdx.x;
    if (e >= NE) return;
    int c = col[e];
    int p = atomicAdd(&cursor[c], 1);
    int o = rowptr[c] + p;
    esrc[o] = row[e];
    ew[o] = nrm[e];
}

// ---------------- CSR aggregation -------------------------------------------
// dst[v] = dinv[v]^2 * f(src[v]) + sum_in-edges w_e * f(src[u]),
// f(x) = inA*x + inD (pending BN affine) or identity.
// Optional epilogue: += obias, relu, and per-column sum/sumsq stats.
__global__ __launch_bounds__(256) void k_agg_csr(
    const float* __restrict__ src, float* __restrict__ dst,
    const int* __restrict__ rowptr, const int* __restrict__ esrc,
    const float* __restrict__ ew, const float* __restrict__ dinv,
    const float* __restrict__ inA, const float* __restrict__ inD,
    const float* __restrict__ obias, int orelu,
    float* __restrict__ ps, float* __restrict__ pq, int F)
{
    int warp = threadIdx.x >> 5, lane = threadIdx.x & 31;
    int v = blockIdx.x * 8 + warp;
    int c0 = blockIdx.y * 64 + lane * 2;
    bool ok0 = c0 < F, ok1 = (c0 + 1) < F;
    float a0 = 1.0f, a1 = 1.0f, d0 = 0.0f, d1 = 0.0f;
    if (inA) {
        if (ok0) { a0 = inA[c0]; d0 = inD[c0]; }
        if (ok1) { a1 = inA[c0 + 1]; d1 = inD[c0 + 1]; }
    }
    float s0 = 0.0f, s1 = 0.0f;
    if (v < NN) {
        float dv = dinv[v];
        float w = dv * dv;
        const float* r = src + (long)v * F + c0;
        if (ok0) s0 = w * fmaf(a0, r[0], d0);
        if (ok1) s1 = w * fmaf(a1, r[1], d1);
        int k0 = rowptr[v], k1 = rowptr[v + 1];
        for (int k = k0; k < k1; k++) {
            int u = esrc[k];
            float we = ew[k];
            const float* ru = src + (long)u * F + c0;
            if (ok0) s0 += we * fmaf(a0, ru[0], d0);
            if (ok1) s1 += we * fmaf(a1, ru[1], d1);
        }
        if (obias) {
            if (ok0) s0 += obias[c0];
            if (ok1) s1 += obias[c0 + 1];
        }
        if (orelu) { s0 = fmaxf(s0, 0.0f); s1 = fmaxf(s1, 0.0f); }
        if (ok0) dst[(long)v * F + c0] = s0;
        if (ok1) dst[(long)v * F + c0 + 1] = s1;
    }
    if (ps) {
        __shared__ float ss[64], sq[64];
        if (threadIdx.x < 64) { ss[threadIdx.x] = 0.0f; sq[threadIdx.x] = 0.0f; }
        __syncthreads();
        if (v < NN) {
            if (ok0) { atomicAdd(&ss[lane * 2], s0); atomicAdd(&sq[lane * 2], s0 * s0); }
            if (ok1) { atomicAdd(&ss[lane * 2 + 1], s1); atomicAdd(&sq[lane * 2 + 1], s1 * s1); }
        }
        __syncthreads();
        int c = blockIdx.y * 64 + threadIdx.x;
        if (threadIdx.x < 64 && c < F) {
            atomicAdd(&ps[c], ss[threadIdx.x]);
            atomicAdd(&pq[c], sq[threadIdx.x]);
        }
    }
}

// ---------------- 3xTF32 tensor-core GEMM ----------------------------------
// C = f(A) @ W (+bias, relu), f = pending BN affine on A's columns (or id).
// Optional per-output-column sum/sumsq stats for the next BN.
__device__ __forceinline__ void tf32split(float x, uint32_t& hi, uint32_t& lo) {
    uint32_t h;
    asm("cvt.rna.tf32.f32 %0, %1;" : "=r"(h) : "f"(x));
    float r = x - __uint_as_float(h);
    uint32_t l;
    asm("cvt.rna.tf32.f32 %0, %1;" : "=r"(l) : "f"(r));
    hi = h;
    lo = l;
}

__device__ __forceinline__ void mma_tf32(float* d, const uint32_t* a, const uint32_t* b) {
    asm volatile(
        "mma.sync.aligned.m16n8k8.row.col.f32.tf32.tf32.f32 "
        "{%0,%1,%2,%3}, {%4,%5,%6,%7}, {%8,%9}, {%0,%1,%2,%3};"
        : "+f"(d[0]), "+f"(d[1]), "+f"(d[2]), "+f"(d[3])
        : "r"(a[0]), "r"(a[1]), "r"(a[2]), "r"(a[3]), "r"(b[0]), "r"(b[1]));
}

__global__ __launch_bounds__(256) void k_gemm_tf32x3(
    const float* __restrict__ A, const float* __restrict__ W,
    const float* __restrict__ bias, float* __restrict__ C,
    const float* __restrict__ inA, const float* __restrict__ inD,
    float* __restrict__ ps, float* __restrict__ pq,
    int M, int N, int K, int doRelu)
{
    __shared__ float As[2][16][132];
    __shared__ float Bs[2][16][132];
    __shared__ float s_sum[128], s_sq[128];
    const int tid = threadIdx.x;
    const int warp = tid >> 5, lane = tid & 31;
    const int wm = warp >> 2, wn = warp & 3;
    const int gr = lane >> 2, gk = lane & 3;
    const int bm = blockIdx.y * 128, bn = blockIdx.x * 128;

    float acc[4][4][4];
#pragma unroll
    for (int i = 0; i < 4; i++)
#pragma unroll
        for (int j = 0; j < 4; j++)
#pragma unroll
            for (int r = 0; r < 4; r++) acc[i][j][r] = 0.0f;

    const int nc = (K + 15) / 16;
    const bool vec = (K & 15) == 0;

    const int ar = tid >> 2, aq = tid & 3;
    const int wr = tid >> 5, wc = (tid & 31) * 4;

    float ra[8];
    float rb[8];

    auto fetch = [&](int c) {
        int k0 = c * 16;
        if (vec) {
            int g0 = bm + ar, g1 = bm + ar + 64;
            if (g0 < M) {
                float4 v = *(const float4*)(A + (long)g0 * K + k0 + aq * 4);
                ra[0] = v.x; ra[1] = v.y; ra[2] = v.z; ra[3] = v.w;
            } else ra[0] = ra[1] = ra[2] = ra[3] = 0.0f;
            if (g1 < M) {
                float4 v = *(const float4*)(A + (long)g1 * K + k0 + aq * 4);
                ra[4] = v.x; ra[5] = v.y; ra[6] = v.z; ra[7] = v.w;
            } else ra[4] = ra[5] = ra[6] = ra[7] = 0.0f;
            if (inA) {
                float4 av = *(const float4*)(inA + k0 + aq * 4);
                float4 dv = *(const float4*)(inD + k0 + aq * 4);
                ra[0] = fmaf(av.x, ra[0], dv.x); ra[1] = fmaf(av.y, ra[1], dv.y);
                ra[2] = fmaf(av.z, ra[2], dv.z); ra[3] = fmaf(av.w, ra[3], dv.w);
                ra[4] = fmaf(av.x, ra[4], dv.x); ra[5] = fmaf(av.y, ra[5], dv.y);
                ra[6] = fmaf(av.z, ra[6], dv.z); ra[7] = fmaf(av.w, ra[7], dv.w);
            }
        } else {
#pragma unroll
            for (int h = 0; h < 2; h++) {
                int g = bm + ar + h * 64;
#pragma unroll
                for (int q = 0; q < 4; q++) {
                    int kk = k0 + aq * 4 + q;
                    float x = (g < M && kk < K) ? A[(long)g * K + kk] : 0.0f;
                    if (inA && kk < K) x = fmaf(inA[kk], x, inD[kk]);
                    ra[h * 4 + q] = x;
                }
            }
        }
#pragma unroll
        for (int h = 0; h < 2; h++) {
            int kk = k0 + wr + h * 8;
            if (kk < K) {
                float4 v = *(const float4*)(W + (long)kk * N + bn + wc);
                rb[h * 4 + 0] = v.x; rb[h * 4 + 1] = v.y;
                rb[h * 4 + 2] = v.z; rb[h * 4 + 3] = v.w;
            } else rb[h * 4 + 0] = rb[h * 4 + 1] = rb[h * 4 + 2] = rb[h * 4 + 3] = 0.0f;
        }
    };
    auto stage = [&](int buf) {
#pragma unroll
        for (int h = 0; h < 2; h++)
#pragma unroll
            for (int q = 0; q < 4; q++)
                As[buf][aq * 4 + q][ar + h * 64] = ra[h * 4 + q];
#pragma unroll
        for (int h = 0; h < 2; h++) {
            float* p = &Bs[buf][wr + h * 8][wc];
            p[0] = rb[h * 4 + 0];
            p[1] = rb[h * 4 + 1];
            p[2] = rb[h * 4 + 2];
            p[3] = rb[h * 4 + 3];
        }
    };

    fetch(0);
    stage(0);
    __syncthreads();

    for (int c = 0; c < nc; c++) {
        int buf = c & 1;
        if (c + 1 < nc) fetch(c + 1);
#pragma unroll
        for (int kk = 0; kk < 2; kk++) {
            uint32_t ah[4][4], al[4][4], bh[4][2], bl[4][2];
#pragma unroll
            for (int i = 0; i < 4; i++) {
                int m = wm * 64 + i * 16 + gr;
                tf32split(As[buf][kk * 8 + gk][m],      ah[i][0], al[i][0]);
                tf32split(As[buf][kk * 8 + gk][m + 8],  ah[i][1], al[i][1]);
                tf32split(As[buf][kk * 8 + gk + 4][m],      ah[i][2], al[i][2]);
                tf32split(As[buf][kk * 8 + gk + 4][m + 8],  ah[i][3], al[i][3]);
            }
#pragma unroll
            for (int j = 0; j < 4; j++) {
                int n = wn * 32 + j * 8 + gr;
                tf32split(Bs[buf][kk * 8 + gk][n],     bh[j][0], bl[j][0]);
                tf32split(Bs[buf][kk * 8 + gk + 4][n], bh[j][1], bl[j][1]);
            }
#pragma unroll
            for (int i = 0; i < 4; i++)
#pragma unroll
                for (int j = 0; j < 4; j++) {
                    mma_tf32(acc[i][j], al[i], bh[j]);   // lo*hi
                    mma_tf32(acc[i][j], ah[i], bl[j]);   // hi*lo
                    mma_tf32(acc[i][j], ah[i], bh[j]);   // hi*hi
                }
        }
        if (c + 1 < nc) {
            stage((c + 1) & 1);
        }
        __syncthreads();
    }

    // epilogue (+ optional column stats)
    float csum[8], csq[8];
#pragma unroll
    for (int t = 0; t < 8; t++) { csum[t] = 0.0f; csq[t] = 0.0f; }
#pragma unroll
    for (int i = 0; i < 4; i++) {
        int r0 = bm + wm * 64 + i * 16 + gr;
        int r1 = r0 + 8;
#pragma unroll
        for (int j = 0; j < 4; j++) {
            int cc = bn + wn * 32 + j * 8 + gk * 2;
            float b0 = bias ? bias[cc] : 0.0f;
            float b1 = bias ? bias[cc + 1] : 0.0f;
            float v0 = acc[i][j][0] + b0, v1 = acc[i][j][1] + b1;
            float v2 = acc[i][j][2] + b0, v3 = acc[i][j][3] + b1;
            if (doRelu) {
                v0 = fmaxf(v0, 0.0f); v1 = fmaxf(v1, 0.0f);
                v2 = fmaxf(v2, 0.0f); v3 = fmaxf(v3, 0.0f);
            }
            if (r0 < M) {
                *(float2*)(C + (long)r0 * N + cc) = make_float2(v0, v1);
                csum[j * 2] += v0; csq[j * 2] += v0 * v0;
                csum[j * 2 + 1] += v1; csq[j * 2 + 1] += v1 * v1;
            }
            if (r1 < M) {
                *(float2*)(C + (long)r1 * N + cc) = make_float2(v2, v3);
                csum[j * 2] += v2; csq[j * 2] += v2 * v2;
                csum[j * 2 + 1] += v3; csq[j * 2 + 1] += v3 * v3;
            }
        }
    }
    if (ps) {
        if (tid < 128) { s_sum[tid] = 0.0f; s_sq[tid] = 0.0f; }
        __syncthreads();
#pragma unroll
        for (int j = 0; j < 4; j++) {
            int cl = wn * 32 + j * 8 + gk * 2;
            atomicAdd(&s_sum[cl], csum[j * 2]);
            atomicAdd(&s_sq[cl], csq[j * 2]);
            atomicAdd(&s_sum[cl + 1], csum[j * 2 + 1]);
            atomicAdd(&s_sq[cl + 1], csq[j * 2 + 1]);
        }
        __syncthreads();
        if (tid < 128) {
            atomicAdd(&ps[bn + tid], s_sum[tid]);
            atomicAdd(&pq[bn + tid], s_sq[tid]);
        }
    }
}

// ---------------- BN finalize: stats -> per-feature affine ------------------
__global__ void k_bnfin(const float* __restrict__ ps, const float* __restrict__ pq,
                        const float* __restrict__ gm, const float* __restrict__ bt,
                        float* __restrict__ aA, float* __restrict__ aD, int F) {
    int c = blockIdx.x * blockDim.x + threadIdx.x;
    if (c >= F) return;
    float m = ps[c] / (float)NN;
    float var = pq[c] / (float)NN - m * m;
    float rstd = rsqrtf(fmaxf(var, 0.0f) + 1e-5f);
    float a = gm[c] * rstd;
    aA[c] = a;
    aD[c] = bt[c] - a * m;
}

// ---------------- global attention pooling (with pending affine) ------------
__global__ void k_gate(const float* __restrict__ H, const float* __restrict__ Wg,
                       const float* __restrict__ bg, const float* __restrict__ aA,
                       const float* __restrict__ aD, float* __restrict__ gate) {
    int t = blockIdx.x * blockDim.x + threadIdx.x;
    int v = t >> 5, lane = t & 31;
    if (v >= NN) return;
    const float* h = H + (long)v * 1024;
    float s = 0.0f;
    for (int k = lane; k < 1024; k += 32)
        s += fmaf(aA[k], h[k], aD[k]) * Wg[k];
#pragma unroll
    for (int o = 16; o; o >>= 1) s += __shfl_down_sync(0xffffffffu, s, o);
    if (lane == 0) gate[v] = s + bg[0];
}

__global__ void k_segmax(const float* __restrict__ gate, const int* __restrict__ batch,
                         float* __restrict__ gmax) {
    int i = blockIdx.x * blockDim.x + threadIdx.x;
    if (i >= NN) return;
    float v = gate[i];
    float* addr = &gmax[batch[i]];
    int old = __float_as_int(*addr);
    while (v > __int_as_float(old)) {
        int prev = atomicCAS((int*)addr, old, __float_as_int(v));
        if (prev == old) break;
        old = prev;
    }
}

__global__ void k_exps(float* __restrict__ gate, const int* __restrict__ batch,
                       const float* __restrict__ gmax, float* __restrict__ gsum) {
    int i = blockIdx.x * blockDim.x + threadIdx.x;
    if (i >= NN) return;
    int b = batch[i];
    float e = expf(gate[i] - gmax[b]);
    gate[i] = e;
    atomicAdd(&gsum[b], e);
}

__global__ void k_coef(float* __restrict__ gate, const int* __restrict__ batch,
                       const float* __restrict__ gsum) {
    int i = blockIdx.x * blockDim.x + threadIdx.x;
    if (i >= NN) return;
    gate[i] = gate[i] / gsum[batch[i]];
}

__global__ void k_pool(const float* __restrict__ H, const float* __restrict__ gate,
                       const int* __restrict__ batch, const float* __restrict__ aA,
                       const float* __restrict__ aD, float* __restrict__ pool) {
    long i = (long)blockIdx.x * blockDim.x + threadIdx.x;
    if (i >= (long)NN * 1024) return;
    int v = (int)(i >> 10);
    int f = (int)(i & 1023);
    float val = fmaf(aA[f], H[i], aD[f]);
    atomicAdd(&pool[((long)batch[v] << 10) + f], gate[v] * val);
}

// ---------------- small MLP GEMMs ------------------------------------------
__global__ void k_mlp(const float* __restrict__ X, const float* __restrict__ W,
                      const float* __restrict__ bias, float* __restrict__ Y,
                      int M, int N, int K, int relu) {
    int i = blockIdx.x * blockDim.x + threadIdx.x;
    if (i >= M * N) return;
    int m = i / N, n = i % N;
    float s = bias[n];
    for (int k = 0; k < K; k++) s += X[m * K + k] * W[k * N + n];
    if (relu) s = fmaxf(s, 0.0f);
    Y[i] = s;
}

// ---------------- launch -----------------------------------------------------
extern "C" void kernel_launch(void* const* d_in, const int* in_sizes, int n_in,
                              void* d_out, int out_size) {
    (void)in_sizes; (void)n_in; (void)out_size;
    const float* x = (const float*)d_in[0];
    const int* ei = (const int*)d_in[1];
    const int* row = ei;
    const int* col = ei + NE;
    const int* batch = (const int*)d_in[2];
    const float *W[5], *b[5], *g[5], *be[5];
    for (int i = 0; i < 5; i++) {
        W[i]  = (const float*)d_in[3 + 4 * i];
        b[i]  = (const float*)d_in[4 + 4 * i];
        g[i]  = (const float*)d_in[5 + 4 * i];
        be[i] = (const float*)d_in[6 + 4 * i];
    }
    const float* Wg  = (const float*)d_in[23];
    const float* bg  = (const float*)d_in[24];
    const float* Wf2 = (const float*)d_in[25];
    const float* bf2 = (const float*)d_in[26];
    const float* Wf3 = (const float*)d_in[27];
    const float* bf3 = (const float*)d_in[28];
    const float* Wf4 = (const float*)d_in[29];
    const float* bf4 = (const float*)d_in[30];

    float *A, *B, *deg, *dinv, *nrm, *ps, *pq, *aA, *aD, *ew;
    float *gate, *gmax, *gsum, *pool, *p2, *p3;
    int *cnt, *rowptr, *cursor, *esrc;
    cudaGetSymbolAddress((void**)&A, g_bufA);
    cudaGetSymbolAddress((void**)&B, g_bufB);
    cudaGetSymbolAddress((void**)&deg, g_deg);
    cudaGetSymbolAddress((void**)&dinv, g_dinv);
    cudaGetSymbolAddress((void**)&nrm, g_enorm);
    cudaGetSymbolAddress((void**)&cnt, g_cnt);
    cudaGetSymbolAddress((void**)&rowptr, g_rowptr);
    cudaGetSymbolAddress((void**)&cursor, g_cursor);
    cudaGetSymbolAddress((void**)&esrc, g_esrc);
    cudaGetSymbolAddress((void**)&ew, g_ew);
    cudaGetSymbolAddress((void**)&ps, g_ps);
    cudaGetSymbolAddress((void**)&pq, g_pq);
    cudaGetSymbolAddress((void**)&aA, g_aA);
    cudaGetSymbolAddress((void**)&aD, g_aD);
    cudaGetSymbolAddress((void**)&gate, g_gate);
    cudaGetSymbolAddress((void**)&gmax, g_gmax);
    cudaGetSymbolAddress((void**)&gsum, g_gsum);
    cudaGetSymbolAddress((void**)&pool, g_pool);
    cudaGetSymbolAddress((void**)&p2, g_p2);
    cudaGetSymbolAddress((void**)&p3, g_p3);

    // ---- graph normalization + CSR build (depends only on edge_index) ----
    k_fill<<<(NN + 255) / 256, 256>>>(deg, NN, 1.0f);            // self-loop
    k_deg<<<(NE + 255) / 256, 256>>>(col, deg);
    k_dinv<<<(NN + 255) / 256, 256>>>(deg, dinv, cnt);
    k_enorm<<<(NE + 255) / 256, 256>>>(row, col, dinv, nrm);
    k_scan<<<1, 1024>>>(cnt, rowptr);
    k_filli<<<(NN + 255) / 256, 256>>>(cursor, NN, 0);
    k_scatter<<<(NE + 255) / 256, 256>>>(row, col, nrm, rowptr, cursor, esrc, ew);

    auto agg = [&](const float* src, float* dst, int F, const float* iA, const float* iD,
                   const float* obias, int orelu, bool stats) {
        dim3 gr((NN + 7) / 8, (F + 63) / 64);
        k_agg_csr<<<gr, 256>>>(src, dst, rowptr, esrc, ew, dinv, iA, iD, obias, orelu,
                               stats ? ps : nullptr, stats ? pq : nullptr, F);
    };
    auto gemm = [&](const float* Ain, const float* Win, const float* bias, float* C,
                    const float* iA, const float* iD, bool stats,
                    int M, int Nn, int K, int relu) {
        dim3 gr(Nn / 128, (M + 127) / 128);
        k_gemm_tf32x3<<<gr, 256>>>(Ain, Win, bias, C, iA, iD,
                                   stats ? ps : nullptr, stats ? pq : nullptr,
                                   M, Nn, K, relu);
    };
    auto zstat = [&](int F) { k_fill<<<(2 * F + 255) / 256, 256>>>(ps, 2 * F > 1024 ? 1024 : 2 * F, 0.0f);
                              k_fill<<<(F + 255) / 256, 256>>>(ps, F, 0.0f);
                              k_fill<<<(F + 255) / 256, 256>>>(pq, F, 0.0f); };
    auto bnfin = [&](int layer, int F) {
        k_bnfin<<<(F + 127) / 128, 128>>>(ps, pq, g[layer], be[layer],
                                          aA + layer * 1024, aD + layer * 1024, F);
    };

    // Layer 1 (29 -> 1024): agg(x) -> A; gemm(+b1,relu,stats) -> B = X1
    agg(x, A, 29, nullptr, nullptr, nullptr, 0, false);
    zstat(1024);
    gemm(A, W[0], b[0], B, nullptr, nullptr, true, NN, 1024, 29, 1);
    bnfin(0, 1024);

    // Layer 2 (1024 -> 512): gemm(affine1 on A-load) -> A; agg(+b2,relu,stats) -> B = X2
    gemm(B, W[1], nullptr, A, aA + 0, aD + 0, false, NN, 512, 1024, 0);
    zstat(512);
    agg(A, B, 512, nullptr, nullptr, b[1], 1, true);
    bnfin(1, 512);

    // Layer 3 (512 -> 256): gemm(affine2) -> A; agg(+b3,relu,stats) -> B = X3
    gemm(B, W[2], nullptr, A, aA + 1024, aD + 1024, false, NN, 256, 512, 0);
    zstat(256);
    agg(A, B, 256, nullptr, nullptr, b[2], 1, true);
    bnfin(2, 256);

    // Layer 4 (256 -> 512): agg(affine3 on src) -> A; gemm(+b4,relu,stats) -> B = X4
    agg(B, A, 256, aA + 2048, aD + 2048, nullptr, 0, false);
    zstat(512);
    gemm(A, W[3], b[3], B, nullptr, nullptr, true, NN, 512, 256, 1);
    bnfin(3, 512);

    // Layer 5 (512 -> 1024): agg(affine4) -> A; gemm(+b5,relu,stats) -> B = X5
    agg(B, A, 512, aA + 3072, aD + 3072, nullptr, 0, false);
    zstat(1024);
    gemm(A, W[4], b[4], B, nullptr, nullptr, true, NN, 1024, 512, 1);
    bnfin(4, 1024);

    // ---- global attention pooling (affine5 applied on the fly) ----
    const float* a5A = aA + 4096;
    const float* a5D = aD + 4096;
    k_gate<<<(NN * 32 + 255) / 256, 256>>>(B, Wg, bg, a5A, a5D, gate);
    k_fill<<<(NG + 255) / 256, 256>>>(gmax, NG, -3e38f);
    k_fill<<<(NG + 255) / 256, 256>>>(gsum, NG, 0.0f);
    k_segmax<<<(NN + 255) / 256, 256>>>(gate, batch, gmax);
    k_exps<<<(NN + 255) / 256, 256>>>(gate, batch, gmax, gsum);
    k_coef<<<(NN + 255) / 256, 256>>>(gate, batch, gsum);
    k_fill<<<(NG * 1024 + 255) / 256, 256>>>(pool, (long)NG * 1024, 0.0f);
    k_pool<<<(int)(((long)NN * 1024 + 255) / 256), 256>>>(B, gate, batch, a5A, a5D, pool);

    // ---- MLP head ----
    k_mlp<<<(NG * 128 + 255) / 256, 256>>>(pool, Wf2, bf2, p2, NG, 128, 1024, 1);
    k_mlp<<<(NG * 16 + 255) / 256, 256>>>(p2, Wf3, bf3, p3, NG, 16, 128, 1);
    k_mlp<<<(NG + 255) / 256, 256>>>(p3, Wf4, bf4, (float*)d_out, NG, 1, 16, 0);
}